// round 7
// baseline (speedup 1.0000x reference)
#include <cuda_runtime.h>
#include <cstdint>
#include <math.h>

// Problem constants
#define B_   4
#define N_   1024
#define DM   512
#define H_   8
#define DH_  64
#define DI   2048
#define MROWS (B_*N_)          // 4096
#define QKV3 (3*DM)            // 1536

// ---------------------------------------------------------------------------
// Scratch (device globals)
// ---------------------------------------------------------------------------
__device__ float g_Zn  [MROWS*DM];
__device__ float g_q   [B_*H_*N_*DH_];             // [B,H,N,DH]
__device__ float g_k   [B_*H_*N_*DH_];             // [B,H,N,DH]
__device__ float g_v   [B_*H_*N_*DH_];             // [B,H,N,DH]
__device__ float g_attn[MROWS*DM];
__device__ float g_Z2  [MROWS*DM];
__device__ float g_Zn2 [MROWS*DM];
__device__ float g_Hid [MROWS*DI];

// ---------------------------------------------------------------------------
// Helpers
// ---------------------------------------------------------------------------
__device__ __forceinline__ uint32_t smem_u32(const void* p) {
    uint32_t a;
    asm("{ .reg .u64 t; cvta.to.shared.u64 t, %1; cvt.u32.u64 %0, t; }" : "=r"(a) : "l"(p));
    return a;
}
#define CP_ASYNC16(sa, ga) \
    asm volatile("cp.async.cg.shared.global [%0], [%1], 16;" :: "r"(sa), "l"(ga))
#define CP_COMMIT() asm volatile("cp.async.commit_group;" ::: "memory")
template<int Nw> __device__ __forceinline__ void cp_wait() {
    asm volatile("cp.async.wait_group %0;" :: "n"(Nw) : "memory");
}
__device__ __forceinline__ void mma_tf32(float& c0, float& c1, float& c2, float& c3,
                                         uint32_t a0, uint32_t a1, uint32_t a2, uint32_t a3,
                                         uint32_t b0, uint32_t b1) {
    asm volatile(
        "mma.sync.aligned.m16n8k8.row.col.f32.tf32.tf32.f32 "
        "{%0,%1,%2,%3},{%4,%5,%6,%7},{%8,%9},{%0,%1,%2,%3};"
        : "+f"(c0), "+f"(c1), "+f"(c2), "+f"(c3)
        : "r"(a0), "r"(a1), "r"(a2), "r"(a3), "r"(b0), "r"(b1));
}

// ---------------------------------------------------------------------------
// LayerNorm
// ---------------------------------------------------------------------------
__global__ void ln_kernel(const float* __restrict__ X,
                          const float* __restrict__ g,
                          const float* __restrict__ b,
                          float* __restrict__ Y)
{
    const int row = blockIdx.x;
    const int tid = threadIdx.x;
    const float4* x4 = reinterpret_cast<const float4*>(X + (size_t)row * DM);
    float4 v = x4[tid];
    float s  = v.x + v.y + v.z + v.w;
    float ss = v.x*v.x + v.y*v.y + v.z*v.z + v.w*v.w;
    #pragma unroll
    for (int o = 16; o; o >>= 1) {
        s  += __shfl_xor_sync(0xffffffffu, s,  o);
        ss += __shfl_xor_sync(0xffffffffu, ss, o);
    }
    __shared__ float sh_s[4], sh_ss[4];
    if ((tid & 31) == 0) { sh_s[tid >> 5] = s; sh_ss[tid >> 5] = ss; }
    __syncthreads();
    s  = sh_s[0]  + sh_s[1]  + sh_s[2]  + sh_s[3];
    ss = sh_ss[0] + sh_ss[1] + sh_ss[2] + sh_ss[3];
    const float mu  = s * (1.0f / DM);
    const float var = ss * (1.0f / DM) - mu * mu;
    const float r   = rsqrtf(var + 1e-5f);
    const float4 gv = reinterpret_cast<const float4*>(g)[tid];
    const float4 bv = reinterpret_cast<const float4*>(b)[tid];
    float4 o;
    o.x = (v.x - mu) * r * gv.x + bv.x;
    o.y = (v.y - mu) * r * gv.y + bv.y;
    o.z = (v.z - mu) * r * gv.z + bv.z;
    o.w = (v.w - mu) * r * gv.w + bv.w;
    reinterpret_cast<float4*>(Y + (size_t)row * DM)[tid] = o;
}

// ---------------------------------------------------------------------------
// Fused flash attention (tf32 mma): per (b,h), Q-tile 64 rows, KV-tile 64.
// ---------------------------------------------------------------------------
__global__ void __launch_bounds__(256, 2)
attn_kernel(const float* __restrict__ nm, const float* __restrict__ Dmat,
            const float* __restrict__ mask, const float* __restrict__ gptr,
            float* __restrict__ attn)
{
    extern __shared__ float sm[];
    float* Qs  = sm;               // [64][68]
    float* Ks  = Qs + 64 * 68;
    float* Vs  = Ks + 64 * 68;
    float* Ps  = Vs + 64 * 68;
    float* redm = Ps + 64 * 68;    // [4][64]
    float* reds = redm + 256;      // [4][64]

    const int tid = threadIdx.x, lane = tid & 31, wid = tid >> 5;
    const int g = lane >> 2, t = lane & 3;
    const int wrow = (wid >> 2) * 32;
    const int wcol = (wid & 3) * 16;
    const int bh = blockIdx.y, b = bh >> 3, h = bh & 7;
    const int q0 = blockIdx.x * 64;
    const float gam = gptr[0];

    const float* qg = g_q + ((size_t)bh * N_ + q0) * DH_;
    const float* kg = g_k + (size_t)bh * N_ * DH_;
    const float* vg = g_v + (size_t)bh * N_ * DH_;

    const uint32_t ks_a = smem_u32(Ks);
    const uint32_t vs_a = smem_u32(Vs);

    for (int i = tid; i < 64 * 16; i += 256) {
        const int r = i >> 4, c = i & 15;
        *reinterpret_cast<float4*>(Qs + r * 68 + c * 4) =
            *reinterpret_cast<const float4*>(qg + (size_t)r * DH_ + c * 4);
    }

    float m_run[2][2], l_run[2][2], o[2][2][4];
    #pragma unroll
    for (int mt = 0; mt < 2; mt++)
        #pragma unroll
        for (int hf = 0; hf < 2; hf++) { m_run[mt][hf] = -1e30f; l_run[mt][hf] = 0.f; }
    #pragma unroll
    for (int mt = 0; mt < 2; mt++)
        #pragma unroll
        for (int nt = 0; nt < 2; nt++)
            #pragma unroll
            for (int r = 0; r < 4; r++) o[mt][nt][r] = 0.f;

    for (int it = 0; it < 16; it++) {
        #pragma unroll
        for (int i = tid; i < 64 * 16; i += 256) {
            const int r = i >> 4, c = i & 15;
            CP_ASYNC16(ks_a + (uint32_t)(r * 68 + c * 4) * 4u,
                       kg + (size_t)(it * 64 + r) * DH_ + c * 4);
        }
        #pragma unroll
        for (int i = tid; i < 64 * 16; i += 256) {
            const int r = i >> 4, c = i & 15;
            CP_ASYNC16(vs_a + (uint32_t)(r * 68 + c * 4) * 4u,
                       vg + (size_t)(it * 64 + r) * DH_ + c * 4);
        }
        CP_COMMIT();
        cp_wait<0>();
        __syncthreads();

        float s[2][2][4];
        #pragma unroll
        for (int mt = 0; mt < 2; mt++)
            #pragma unroll
            for (int nt = 0; nt < 2; nt++)
                #pragma unroll
                for (int r = 0; r < 4; r++) s[mt][nt][r] = 0.f;
        {
            const uint32_t* Q32 = reinterpret_cast<const uint32_t*>(Qs);
            const uint32_t* K32 = reinterpret_cast<const uint32_t*>(Ks);
            #pragma unroll
            for (int kk = 0; kk < 8; kk++) {
                uint32_t qa[2][4];
                #pragma unroll
                for (int mt = 0; mt < 2; mt++) {
                    const uint32_t* p = Q32 + (wrow + mt * 16 + g) * 68 + kk * 8 + t;
                    qa[mt][0] = p[0]; qa[mt][1] = p[8 * 68];
                    qa[mt][2] = p[4]; qa[mt][3] = p[8 * 68 + 4];
                }
                uint32_t kb[2][2];
                #pragma unroll
                for (int nt = 0; nt < 2; nt++) {
                    const uint32_t* p = K32 + (wcol + nt * 8 + g) * 68 + kk * 8 + t;
                    kb[nt][0] = p[0]; kb[nt][1] = p[4];
                }
                #pragma unroll
                for (int mt = 0; mt < 2; mt++)
                    #pragma unroll
                    for (int nt = 0; nt < 2; nt++)
                        mma_tf32(s[mt][nt][0], s[mt][nt][1], s[mt][nt][2], s[mt][nt][3],
                                 qa[mt][0], qa[mt][1], qa[mt][2], qa[mt][3],
                                 kb[nt][0], kb[nt][1]);
            }
        }

        float pm[2][2] = {{-1e30f, -1e30f}, {-1e30f, -1e30f}};
        #pragma unroll
        for (int mt = 0; mt < 2; mt++)
            #pragma unroll
            for (int hf = 0; hf < 2; hf++)
                #pragma unroll
                for (int nt = 0; nt < 2; nt++) {
                    const int row = q0 + wrow + mt * 16 + hf * 8 + g;
                    const int col = it * 64 + wcol + nt * 8 + 2 * t;
                    const size_t base = ((size_t)b * N_ + row) * N_ + col;
                    float2 nmv = *reinterpret_cast<const float2*>(nm + base);
                    float2 dv  = *reinterpret_cast<const float2*>(Dmat + base);
                    float x0 = s[mt][nt][hf * 2 + 0] * 0.125f + nmv.x - gam * dv.x;
                    float x1 = s[mt][nt][hf * 2 + 1] * 0.125f + nmv.y - gam * dv.y;
                    s[mt][nt][hf * 2 + 0] = x0;
                    s[mt][nt][hf * 2 + 1] = x1;
                    pm[mt][hf] = fmaxf(pm[mt][hf], fmaxf(x0, x1));
                }
        #pragma unroll
        for (int x = 1; x <= 2; x <<= 1)
            #pragma unroll
            for (int mt = 0; mt < 2; mt++)
                #pragma unroll
                for (int hf = 0; hf < 2; hf++)
                    pm[mt][hf] = fmaxf(pm[mt][hf], __shfl_xor_sync(0xffffffffu, pm[mt][hf], x));
        if (t == 0) {
            #pragma unroll
            for (int mt = 0; mt < 2; mt++)
                #pragma unroll
                for (int hf = 0; hf < 2; hf++)
                    redm[(wid & 3) * 64 + wrow + mt * 16 + hf * 8 + g] = pm[mt][hf];
        }
        __syncthreads();

        float m_new[2][2], scale[2][2];
        #pragma unroll
        for (int mt = 0; mt < 2; mt++)
            #pragma unroll
            for (int hf = 0; hf < 2; hf++) {
                const int r = wrow + mt * 16 + hf * 8 + g;
                float mx = fmaxf(fmaxf(redm[r], redm[64 + r]),
                                 fmaxf(redm[128 + r], redm[192 + r]));
                m_new[mt][hf] = fmaxf(m_run[mt][hf], mx);
                scale[mt][hf] = __expf(m_run[mt][hf] - m_new[mt][hf]);
            }

        float ps[2][2] = {{0.f, 0.f}, {0.f, 0.f}};
        #pragma unroll
        for (int mt = 0; mt < 2; mt++)
            #pragma unroll
            for (int hf = 0; hf < 2; hf++)
                #pragma unroll
                for (int nt = 0; nt < 2; nt++) {
                    float e0 = __expf(s[mt][nt][hf * 2 + 0] - m_new[mt][hf]);
                    float e1 = __expf(s[mt][nt][hf * 2 + 1] - m_new[mt][hf]);
                    s[mt][nt][hf * 2 + 0] = e0;
                    s[mt][nt][hf * 2 + 1] = e1;
                    ps[mt][hf] += e0 + e1;
                }
        #pragma unroll
        for (int x = 1; x <= 2; x <<= 1)
            #pragma unroll
            for (int mt = 0; mt < 2; mt++)
                #pragma unroll
                for (int hf = 0; hf < 2; hf++)
                    ps[mt][hf] += __shfl_xor_sync(0xffffffffu, ps[mt][hf], x);
        if (t == 0) {
            #pragma unroll
            for (int mt = 0; mt < 2; mt++)
                #pragma unroll
                for (int hf = 0; hf < 2; hf++)
                    reds[(wid & 3) * 64 + wrow + mt * 16 + hf * 8 + g] = ps[mt][hf];
        }

        #pragma unroll
        for (int mt = 0; mt < 2; mt++)
            #pragma unroll
            for (int hf = 0; hf < 2; hf++)
                #pragma unroll
                for (int nt = 0; nt < 2; nt++) {
                    const int row = q0 + wrow + mt * 16 + hf * 8 + g;
                    const int col = it * 64 + wcol + nt * 8 + 2 * t;
                    const size_t base = ((size_t)b * N_ + row) * N_ + col;
                    float2 mv = *reinterpret_cast<const float2*>(mask + base);
                    float2 pv = make_float2(s[mt][nt][hf * 2 + 0] * mv.x,
                                            s[mt][nt][hf * 2 + 1] * mv.y);
                    *reinterpret_cast<float2*>(
                        Ps + (wrow + mt * 16 + hf * 8 + g) * 68 + wcol + nt * 8 + 2 * t) = pv;
                }
        __syncthreads();

        #pragma unroll
        for (int mt = 0; mt < 2; mt++)
            #pragma unroll
            for (int hf = 0; hf < 2; hf++) {
                const int r = wrow + mt * 16 + hf * 8 + g;
                const float rowsum = reds[r] + reds[64 + r] + reds[128 + r] + reds[192 + r];
                l_run[mt][hf] = l_run[mt][hf] * scale[mt][hf] + rowsum;
                m_run[mt][hf] = m_new[mt][hf];
            }
        #pragma unroll
        for (int mt = 0; mt < 2; mt++)
            #pragma unroll
            for (int nt = 0; nt < 2; nt++)
                #pragma unroll
                for (int r = 0; r < 4; r++)
                    o[mt][nt][r] *= scale[mt][r >> 1];

        {
            const uint32_t* P32 = reinterpret_cast<const uint32_t*>(Ps);
            const uint32_t* V32 = reinterpret_cast<const uint32_t*>(Vs);
            #pragma unroll
            for (int kk = 0; kk < 8; kk++) {
                uint32_t pa[2][4];
                #pragma unroll
                for (int mt = 0; mt < 2; mt++) {
                    const uint32_t* p = P32 + (wrow + mt * 16 + g) * 68 + kk * 8 + t;
                    pa[mt][0] = p[0]; pa[mt][1] = p[8 * 68];
                    pa[mt][2] = p[4]; pa[mt][3] = p[8 * 68 + 4];
                }
                uint32_t vb[2][2];
                #pragma unroll
                for (int nt = 0; nt < 2; nt++) {
                    const uint32_t* p = V32 + (kk * 8 + t) * 68 + wcol + nt * 8 + g;
                    vb[nt][0] = p[0]; vb[nt][1] = p[4 * 68];
                }
                #pragma unroll
                for (int mt = 0; mt < 2; mt++)
                    #pragma unroll
                    for (int nt = 0; nt < 2; nt++)
                        mma_tf32(o[mt][nt][0], o[mt][nt][1], o[mt][nt][2], o[mt][nt][3],
                                 pa[mt][0], pa[mt][1], pa[mt][2], pa[mt][3],
                                 vb[nt][0], vb[nt][1]);
            }
        }
        __syncthreads();
    }

    #pragma unroll
    for (int mt = 0; mt < 2; mt++)
        #pragma unroll
        for (int hf = 0; hf < 2; hf++) {
            const float inv = 1.0f / l_run[mt][hf];
            const int row = q0 + wrow + mt * 16 + hf * 8 + g;
            float* dst = attn + ((size_t)b * N_ + row) * DM + h * DH_;
            #pragma unroll
            for (int nt = 0; nt < 2; nt++) {
                const int d = wcol + nt * 8 + 2 * t;
                float v0 = o[mt][nt][hf * 2 + 0] * inv;
                float v1 = o[mt][nt][hf * 2 + 1] * inv;
                v0 = v0 > 0.f ? v0 : 0.01f * v0;
                v1 = v1 > 0.f ? v1 : 0.01f * v1;
                *reinterpret_cast<float2*>(dst + d) = make_float2(v0, v1);
            }
        }
}

// ---------------------------------------------------------------------------
// tf32 mma.sync GEMM: C = A(MxK) * B(NxK)^T. BM=64, BN=64, BK=32.
// 128 threads = 4 warps (2x2), warp tile 32x32. 3-stage cp.async ring.
//   EPI 1: QKV scatter (+bias)   EPI 4: +bias? +residual   EPI 5: +bias, relu
// ---------------------------------------------------------------------------
template<int EPI>
__global__ void __launch_bounds__(128, 4)
tc_gemm(const float* __restrict__ A, const float* __restrict__ Bm,
        const float* __restrict__ bias, float* __restrict__ C,
        int M, int N, int K,
        const float* __restrict__ e1)
{
    constexpr int THREADS = 128;
    constexpr int LDA     = 36;
    constexpr int STG     = 128 * LDA;     // A(64)+B(64) rows per stage

    extern __shared__ float sm[];

    const int tid  = threadIdx.x;
    const int wid  = tid >> 5;
    const int lane = tid & 31;
    const int g    = lane >> 2;
    const int t    = lane & 3;
    const int wr   = (wid >> 1) * 32;      // 0 or 32
    const int wc   = (wid & 1) * 32;       // 0 or 32

    const int brow = blockIdx.y * 64;
    const int bcol = blockIdx.x * 64;
    const float* Ab = A  + (size_t)brow * K;
    const float* Bb = Bm + (size_t)bcol * K;

    float c[2][4][4];
    #pragma unroll
    for (int i = 0; i < 2; i++)
        #pragma unroll
        for (int j = 0; j < 4; j++)
            #pragma unroll
            for (int r = 0; r < 4; r++) c[i][j][r] = 0.0f;

    const uint32_t smb = smem_u32(sm);

    auto load_stage = [&](int s) {
        const int buf = s % 3;
        const uint32_t as = smb + (uint32_t)(buf * STG) * 4u;
        const uint32_t bs = as + 64u * LDA * 4u;
        const float* ag = Ab + s * 32;
        #pragma unroll
        for (int i = tid; i < 64 * 8; i += THREADS) {
            const int r = i >> 3, q = i & 7;
            CP_ASYNC16(as + (uint32_t)(r * LDA + q * 4) * 4u,
                       ag + (size_t)r * K + q * 4);
        }
        const float* bg = Bb + s * 32;
        #pragma unroll
        for (int i = tid; i < 64 * 8; i += THREADS) {
            const int r = i >> 3, q = i & 7;
            CP_ASYNC16(bs + (uint32_t)(r * LDA + q * 4) * 4u,
                       bg + (size_t)r * K + q * 4);
        }
        CP_COMMIT();
    };

    const int S = K / 32;
    load_stage(0);
    if (S > 1) load_stage(1);

    for (int s = 0; s < S; s++) {
        cp_wait<1>();
        __syncthreads();
        if (s + 2 < S) load_stage(s + 2);

        const int buf = s % 3;
        const uint32_t* As32 = reinterpret_cast<const uint32_t*>(sm + buf * STG);
        const uint32_t* Bs32 = As32 + 64 * LDA;

        #pragma unroll
        for (int kk = 0; kk < 4; kk++) {
            const int k = kk * 8;
            uint32_t af[2][4];
            #pragma unroll
            for (int mt = 0; mt < 2; mt++) {
                const uint32_t* p0 = As32 + (wr + mt * 16 + g) * LDA + k + t;
                const uint32_t* p1 = p0 + 8 * LDA;
                af[mt][0] = p0[0]; af[mt][1] = p1[0];
                af[mt][2] = p0[4]; af[mt][3] = p1[4];
            }
            uint32_t bf[4][2];
            #pragma unroll
            for (int nt = 0; nt < 4; nt++) {
                const uint32_t* p = Bs32 + (wc + nt * 8 + g) * LDA + k + t;
                bf[nt][0] = p[0]; bf[nt][1] = p[4];
            }
            #pragma unroll
            for (int mt = 0; mt < 2; mt++)
                #pragma unroll
                for (int nt = 0; nt < 4; nt++)
                    mma_tf32(c[mt][nt][0], c[mt][nt][1], c[mt][nt][2], c[mt][nt][3],
                             af[mt][0], af[mt][1], af[mt][2], af[mt][3],
                             bf[nt][0], bf[nt][1]);
        }
        __syncthreads();
    }

    #pragma unroll
    for (int mt = 0; mt < 2; mt++) {
        #pragma unroll
        for (int half = 0; half < 2; half++) {
            const int row = brow + wr + mt * 16 + g + half * 8;
            #pragma unroll
            for (int nt = 0; nt < 4; nt++) {
                const int col = bcol + wc + nt * 8 + 2 * t;
                float v0 = c[mt][nt][half * 2 + 0];
                float v1 = c[mt][nt][half * 2 + 1];
                if constexpr (EPI == 1) {
                    v0 += bias[col]; v1 += bias[col + 1];
                    const int h  = col / (3 * DH_);
                    const int cc = col % (3 * DH_);
                    const int bb = row >> 10;
                    const int n  = row & (N_ - 1);
                    float* dst;
                    if (cc < DH_)
                        dst = g_v + ((size_t)(bb * H_ + h) * N_ + n) * DH_ + cc;
                    else if (cc < 2 * DH_)
                        dst = g_q + ((size_t)(bb * H_ + h) * N_ + n) * DH_ + (cc - DH_);
                    else
                        dst = g_k + ((size_t)(bb * H_ + h) * N_ + n) * DH_ + (cc - 2 * DH_);
                    *reinterpret_cast<float2*>(dst) = make_float2(v0, v1);
                } else if constexpr (EPI == 4) {
                    if (bias) { v0 += bias[col]; v1 += bias[col + 1]; }
                    float2 r2 = *reinterpret_cast<const float2*>(e1 + (size_t)row * N + col);
                    *reinterpret_cast<float2*>(C + (size_t)row * N + col) =
                        make_float2(v0 + r2.x, v1 + r2.y);
                } else {  // EPI 5
                    v0 += bias[col]; v1 += bias[col + 1];
                    *reinterpret_cast<float2*>(C + (size_t)row * N + col) =
                        make_float2(fmaxf(v0, 0.f), fmaxf(v1, 0.f));
                }
            }
        }
    }
}

// ---------------------------------------------------------------------------
// Launch
// ---------------------------------------------------------------------------
extern "C" void kernel_launch(void* const* d_in, const int* in_sizes, int n_in,
                              void* d_out, int out_size)
{
    const float* Z        = (const float*)d_in[0];
    const float* Dm       = (const float*)d_in[1];
    const float* new_mask = (const float*)d_in[2];
    const float* mask     = (const float*)d_in[3];
    const float* Wqkv     = (const float*)d_in[4];
    const float* bqkv     = (const float*)d_in[5];
    const float* Wo       = (const float*)d_in[6];
    const float* g1       = (const float*)d_in[7];
    const float* b1       = (const float*)d_in[8];
    const float* g2       = (const float*)d_in[9];
    const float* b2       = (const float*)d_in[10];
    const float* Wp1      = (const float*)d_in[11];
    const float* bp1      = (const float*)d_in[12];
    const float* Wp2      = (const float*)d_in[13];
    const float* bp2      = (const float*)d_in[14];
    const float* gamma    = (const float*)d_in[15];
    float* out = (float*)d_out;

    float *pZn, *pattn, *pZ2, *pZn2, *pHid;
    cudaGetSymbolAddress((void**)&pZn,   g_Zn);
    cudaGetSymbolAddress((void**)&pattn, g_attn);
    cudaGetSymbolAddress((void**)&pZ2,   g_Z2);
    cudaGetSymbolAddress((void**)&pZn2,  g_Zn2);
    cudaGetSymbolAddress((void**)&pHid,  g_Hid);

    const int SMG   = 3 * 128 * 36 * 4;          // 55296
    const int SMATT = (4 * 64 * 68 + 512) * 4;   // 71680
    cudaFuncSetAttribute(tc_gemm<1>, cudaFuncAttributeMaxDynamicSharedMemorySize, SMG);
    cudaFuncSetAttribute(tc_gemm<4>, cudaFuncAttributeMaxDynamicSharedMemorySize, SMG);
    cudaFuncSetAttribute(tc_gemm<5>, cudaFuncAttributeMaxDynamicSharedMemorySize, SMG);
    cudaFuncSetAttribute(attn_kernel, cudaFuncAttributeMaxDynamicSharedMemorySize, SMATT);

    // 1) LN1
    ln_kernel<<<MROWS, 128>>>(Z, g1, b1, pZn);

    // 2) QKV: [4096,512] x [1536,512]^T -> scatter q/k/v
    tc_gemm<1><<<dim3(QKV3/64, MROWS/64), 128, SMG>>>(
        pZn, Wqkv, bqkv, nullptr, MROWS, QKV3, DM, nullptr);

    // 3) Fused flash attention -> g_attn
    attn_kernel<<<dim3(N_/64, B_*H_), 256, SMATT>>>(
        new_mask, Dm, mask, gamma, pattn);

    // 4) Wo + residual
    tc_gemm<4><<<dim3(DM/64, MROWS/64), 128, SMG>>>(
        pattn, Wo, nullptr, pZ2, MROWS, DM, DM, Z);

    // 5) LN2
    ln_kernel<<<MROWS, 128>>>(pZ2, g2, b2, pZn2);

    // 6) MLP1 + relu
    tc_gemm<5><<<dim3(DI/64, MROWS/64), 128, SMG>>>(
        pZn2, Wp1, bp1, pHid, MROWS, DI, DM, nullptr);

    // 7) MLP2 + bias + residual -> out
    tc_gemm<4><<<dim3(DM/64, MROWS/64), 128, SMG>>>(
        pHid, Wp2, bp2, out, MROWS, DM, DI, pZ2);
}

// round 8
// speedup vs baseline: 1.5427x; 1.5427x over previous
#include <cuda_runtime.h>
#include <cuda_fp16.h>
#include <cstdint>
#include <math.h>

#define B_   4
#define N_   1024
#define DM   512
#define H_   8
#define DH_  64
#define DI   2048
#define MROWS (B_*N_)          // 4096
#define QKV3 (3*DM)            // 1536

// ---------------------------------------------------------------------------
// Scratch (device globals)
// ---------------------------------------------------------------------------
__device__ __half g_Znh [MROWS*DM];
__device__ __half g_hq  [B_*H_*N_*DH_];     // [B,H,N,DH]
__device__ __half g_hk  [B_*H_*N_*DH_];     // [B,H,N,DH]
__device__ __half g_hvT [B_*H_*DH_*N_];     // [B,H,DH,N]
__device__ __half g_attnh[MROWS*DM];
__device__ float  g_Z2  [MROWS*DM];
__device__ __half g_Zn2h[MROWS*DM];
__device__ __half g_Hidh[MROWS*DI];
__device__ __half g_hWqkv[QKV3*DM];
__device__ __half g_hWo [DM*DM];
__device__ __half g_hWp1[DI*DM];
__device__ __half g_hWp2[DM*DI];

// ---------------------------------------------------------------------------
// Helpers
// ---------------------------------------------------------------------------
__device__ __forceinline__ uint32_t smem_u32(const void* p) {
    uint32_t a;
    asm("{ .reg .u64 t; cvta.to.shared.u64 t, %1; cvt.u32.u64 %0, t; }" : "=r"(a) : "l"(p));
    return a;
}
#define CP_ASYNC16(sa, ga) \
    asm volatile("cp.async.cg.shared.global [%0], [%1], 16;" :: "r"(sa), "l"(ga))
#define CP_COMMIT() asm volatile("cp.async.commit_group;" ::: "memory")
template<int Nw> __device__ __forceinline__ void cp_wait() {
    asm volatile("cp.async.wait_group %0;" :: "n"(Nw) : "memory");
}
__device__ __forceinline__ void mma_f16(float& c0, float& c1, float& c2, float& c3,
                                        uint32_t a0, uint32_t a1, uint32_t a2, uint32_t a3,
                                        uint32_t b0, uint32_t b1) {
    asm volatile(
        "mma.sync.aligned.m16n8k16.row.col.f32.f16.f16.f32 "
        "{%0,%1,%2,%3},{%4,%5,%6,%7},{%8,%9},{%0,%1,%2,%3};"
        : "+f"(c0), "+f"(c1), "+f"(c2), "+f"(c3)
        : "r"(a0), "r"(a1), "r"(a2), "r"(a3), "r"(b0), "r"(b1));
}

// ---------------------------------------------------------------------------
// float -> half conversion (weights)
// ---------------------------------------------------------------------------
__global__ void f2h_kernel(const float* __restrict__ s, __half* __restrict__ d, int n4)
{
    const int i = blockIdx.x * 256 + threadIdx.x;
    if (i < n4) {
        float4 v = reinterpret_cast<const float4*>(s)[i];
        __half2 h0 = __floats2half2_rn(v.x, v.y);
        __half2 h1 = __floats2half2_rn(v.z, v.w);
        reinterpret_cast<__half2*>(d)[2 * i]     = h0;
        reinterpret_cast<__half2*>(d)[2 * i + 1] = h1;
    }
}

// ---------------------------------------------------------------------------
// LayerNorm: fp32 in -> fp16 out
// ---------------------------------------------------------------------------
__global__ void ln_kernel(const float* __restrict__ X,
                          const float* __restrict__ g,
                          const float* __restrict__ b,
                          __half* __restrict__ Y)
{
    const int row = blockIdx.x;
    const int tid = threadIdx.x;
    const float4* x4 = reinterpret_cast<const float4*>(X + (size_t)row * DM);
    float4 v = x4[tid];
    float s  = v.x + v.y + v.z + v.w;
    float ss = v.x*v.x + v.y*v.y + v.z*v.z + v.w*v.w;
    #pragma unroll
    for (int o = 16; o; o >>= 1) {
        s  += __shfl_xor_sync(0xffffffffu, s,  o);
        ss += __shfl_xor_sync(0xffffffffu, ss, o);
    }
    __shared__ float sh_s[4], sh_ss[4];
    if ((tid & 31) == 0) { sh_s[tid >> 5] = s; sh_ss[tid >> 5] = ss; }
    __syncthreads();
    s  = sh_s[0]  + sh_s[1]  + sh_s[2]  + sh_s[3];
    ss = sh_ss[0] + sh_ss[1] + sh_ss[2] + sh_ss[3];
    const float mu  = s * (1.0f / DM);
    const float var = ss * (1.0f / DM) - mu * mu;
    const float r   = rsqrtf(var + 1e-5f);
    const float4 gv = reinterpret_cast<const float4*>(g)[tid];
    const float4 bv = reinterpret_cast<const float4*>(b)[tid];
    __half2 h0 = __floats2half2_rn((v.x - mu) * r * gv.x + bv.x,
                                   (v.y - mu) * r * gv.y + bv.y);
    __half2 h1 = __floats2half2_rn((v.z - mu) * r * gv.z + bv.z,
                                   (v.w - mu) * r * gv.w + bv.w);
    __half2* y2 = reinterpret_cast<__half2*>(Y + (size_t)row * DM);
    y2[2 * tid]     = h0;
    y2[2 * tid + 1] = h1;
}

// ---------------------------------------------------------------------------
// Fused flash attention, fp16 mma (m16n8k16). Per (b,h), Q-tile 64, KV-tile 64.
// Smem rows padded to 36 b32 words (conflict-free 4g+t bank pattern).
// ---------------------------------------------------------------------------
#define LDW 36
__global__ void __launch_bounds__(256, 2)
attn_kernel(const float* __restrict__ nm, const float* __restrict__ Dmat,
            const float* __restrict__ mask, const float* __restrict__ gptr,
            __half* __restrict__ attn)
{
    extern __shared__ uint32_t sw[];
    uint32_t* Qs  = sw;               // [64][36] words
    uint32_t* Ks  = Qs + 64 * LDW;
    uint32_t* Vt  = Ks + 64 * LDW;    // V^T: rows d, cols kv
    uint32_t* Ps  = Vt + 64 * LDW;
    float* redm = reinterpret_cast<float*>(Ps + 64 * LDW);   // [4][64]
    float* reds = redm + 256;

    const int tid = threadIdx.x, lane = tid & 31, wid = tid >> 5;
    const int g = lane >> 2, t = lane & 3;
    const int wrow = (wid >> 2) * 32;
    const int wcol = (wid & 3) * 16;
    const int bh = blockIdx.y, b = bh >> 3, h = bh & 7;
    const int q0 = blockIdx.x * 64;
    const float gam = gptr[0];

    const __half* qg = g_hq + ((size_t)bh * N_ + q0) * DH_;
    const __half* kg = g_hk + (size_t)bh * N_ * DH_;
    const __half* vg = g_hvT + (size_t)bh * DH_ * N_;

    const uint32_t qs_a = smem_u32(Qs);
    const uint32_t ks_a = smem_u32(Ks);
    const uint32_t vt_a = smem_u32(Vt);

    // Load Q tile: 64 rows x 64 halfs (8 chunks of 16B per row)
    #pragma unroll
    for (int i = tid; i < 64 * 8; i += 256) {
        const int r = i >> 3, q = i & 7;
        CP_ASYNC16(qs_a + (uint32_t)(r * LDW + q * 4) * 4u, qg + (size_t)r * DH_ + q * 8);
    }
    CP_COMMIT();

    float m_run[2][2], l_run[2][2], o[2][2][4];
    #pragma unroll
    for (int mt = 0; mt < 2; mt++)
        #pragma unroll
        for (int hf = 0; hf < 2; hf++) { m_run[mt][hf] = -1e30f; l_run[mt][hf] = 0.f; }
    #pragma unroll
    for (int mt = 0; mt < 2; mt++)
        #pragma unroll
        for (int nt = 0; nt < 2; nt++)
            #pragma unroll
            for (int r = 0; r < 4; r++) o[mt][nt][r] = 0.f;

    for (int it = 0; it < 16; it++) {
        #pragma unroll
        for (int i = tid; i < 64 * 8; i += 256) {
            const int r = i >> 3, q = i & 7;
            CP_ASYNC16(ks_a + (uint32_t)(r * LDW + q * 4) * 4u,
                       kg + (size_t)(it * 64 + r) * DH_ + q * 8);
        }
        #pragma unroll
        for (int i = tid; i < 64 * 8; i += 256) {
            const int r = i >> 3, q = i & 7;   // r = d, cols kv
            CP_ASYNC16(vt_a + (uint32_t)(r * LDW + q * 4) * 4u,
                       vg + (size_t)r * N_ + it * 64 + q * 8);
        }
        CP_COMMIT();
        cp_wait<0>();
        __syncthreads();

        // S = Q @ K^T
        float s[2][2][4];
        #pragma unroll
        for (int mt = 0; mt < 2; mt++)
            #pragma unroll
            for (int nt = 0; nt < 2; nt++)
                #pragma unroll
                for (int r = 0; r < 4; r++) s[mt][nt][r] = 0.f;
        #pragma unroll
        for (int kk = 0; kk < 4; kk++) {
            const int kb = kk * 8;
            uint32_t qa[2][4];
            #pragma unroll
            for (int mt = 0; mt < 2; mt++) {
                const uint32_t* p0 = Qs + (wrow + mt * 16 + g) * LDW + kb + t;
                const uint32_t* p1 = p0 + 8 * LDW;
                qa[mt][0] = p0[0]; qa[mt][1] = p1[0];
                qa[mt][2] = p0[4]; qa[mt][3] = p1[4];
            }
            uint32_t kb_[2][2];
            #pragma unroll
            for (int nt = 0; nt < 2; nt++) {
                const uint32_t* p = Ks + (wcol + nt * 8 + g) * LDW + kb + t;
                kb_[nt][0] = p[0]; kb_[nt][1] = p[4];
            }
            #pragma unroll
            for (int mt = 0; mt < 2; mt++)
                #pragma unroll
                for (int nt = 0; nt < 2; nt++)
                    mma_f16(s[mt][nt][0], s[mt][nt][1], s[mt][nt][2], s[mt][nt][3],
                            qa[mt][0], qa[mt][1], qa[mt][2], qa[mt][3],
                            kb_[nt][0], kb_[nt][1]);
        }

        // bias + row max
        float pm[2][2] = {{-1e30f, -1e30f}, {-1e30f, -1e30f}};
        #pragma unroll
        for (int mt = 0; mt < 2; mt++)
            #pragma unroll
            for (int hf = 0; hf < 2; hf++)
                #pragma unroll
                for (int nt = 0; nt < 2; nt++) {
                    const int row = q0 + wrow + mt * 16 + hf * 8 + g;
                    const int col = it * 64 + wcol + nt * 8 + 2 * t;
                    const size_t base = ((size_t)b * N_ + row) * N_ + col;
                    float2 nmv = *reinterpret_cast<const float2*>(nm + base);
                    float2 dv  = *reinterpret_cast<const float2*>(Dmat + base);
                    float x0 = s[mt][nt][hf * 2 + 0] * 0.125f + nmv.x - gam * dv.x;
                    float x1 = s[mt][nt][hf * 2 + 1] * 0.125f + nmv.y - gam * dv.y;
                    s[mt][nt][hf * 2 + 0] = x0;
                    s[mt][nt][hf * 2 + 1] = x1;
                    pm[mt][hf] = fmaxf(pm[mt][hf], fmaxf(x0, x1));
                }
        #pragma unroll
        for (int x = 1; x <= 2; x <<= 1)
            #pragma unroll
            for (int mt = 0; mt < 2; mt++)
                #pragma unroll
                for (int hf = 0; hf < 2; hf++)
                    pm[mt][hf] = fmaxf(pm[mt][hf], __shfl_xor_sync(0xffffffffu, pm[mt][hf], x));
        if (t == 0) {
            #pragma unroll
            for (int mt = 0; mt < 2; mt++)
                #pragma unroll
                for (int hf = 0; hf < 2; hf++)
                    redm[(wid & 3) * 64 + wrow + mt * 16 + hf * 8 + g] = pm[mt][hf];
        }
        __syncthreads();

        float m_new[2][2], scale[2][2];
        #pragma unroll
        for (int mt = 0; mt < 2; mt++)
            #pragma unroll
            for (int hf = 0; hf < 2; hf++) {
                const int r = wrow + mt * 16 + hf * 8 + g;
                float mx = fmaxf(fmaxf(redm[r], redm[64 + r]),
                                 fmaxf(redm[128 + r], redm[192 + r]));
                m_new[mt][hf] = fmaxf(m_run[mt][hf], mx);
                scale[mt][hf] = __expf(m_run[mt][hf] - m_new[mt][hf]);
            }

        float ps[2][2] = {{0.f, 0.f}, {0.f, 0.f}};
        #pragma unroll
        for (int mt = 0; mt < 2; mt++)
            #pragma unroll
            for (int hf = 0; hf < 2; hf++)
                #pragma unroll
                for (int nt = 0; nt < 2; nt++) {
                    float e0 = __expf(s[mt][nt][hf * 2 + 0] - m_new[mt][hf]);
                    float e1 = __expf(s[mt][nt][hf * 2 + 1] - m_new[mt][hf]);
                    s[mt][nt][hf * 2 + 0] = e0;
                    s[mt][nt][hf * 2 + 1] = e1;
                    ps[mt][hf] += e0 + e1;
                }
        #pragma unroll
        for (int x = 1; x <= 2; x <<= 1)
            #pragma unroll
            for (int mt = 0; mt < 2; mt++)
                #pragma unroll
                for (int hf = 0; hf < 2; hf++)
                    ps[mt][hf] += __shfl_xor_sync(0xffffffffu, ps[mt][hf], x);
        if (t == 0) {
            #pragma unroll
            for (int mt = 0; mt < 2; mt++)
                #pragma unroll
                for (int hf = 0; hf < 2; hf++)
                    reds[(wid & 3) * 64 + wrow + mt * 16 + hf * 8 + g] = ps[mt][hf];
        }

        // mask, convert to fp16, write P
        #pragma unroll
        for (int mt = 0; mt < 2; mt++)
            #pragma unroll
            for (int hf = 0; hf < 2; hf++)
                #pragma unroll
                for (int nt = 0; nt < 2; nt++) {
                    const int row = q0 + wrow + mt * 16 + hf * 8 + g;
                    const int col = it * 64 + wcol + nt * 8 + 2 * t;
                    const size_t base = ((size_t)b * N_ + row) * N_ + col;
                    float2 mv = *reinterpret_cast<const float2*>(mask + base);
                    __half2 pv = __floats2half2_rn(s[mt][nt][hf * 2 + 0] * mv.x,
                                                   s[mt][nt][hf * 2 + 1] * mv.y);
                    Ps[(wrow + mt * 16 + hf * 8 + g) * LDW + wcol / 2 + nt * 4 + t] =
                        *reinterpret_cast<uint32_t*>(&pv);
                }
        __syncthreads();

        #pragma unroll
        for (int mt = 0; mt < 2; mt++)
            #pragma unroll
            for (int hf = 0; hf < 2; hf++) {
                const int r = wrow + mt * 16 + hf * 8 + g;
                const float rowsum = reds[r] + reds[64 + r] + reds[128 + r] + reds[192 + r];
                l_run[mt][hf] = l_run[mt][hf] * scale[mt][hf] + rowsum;
                m_run[mt][hf] = m_new[mt][hf];
            }
        #pragma unroll
        for (int mt = 0; mt < 2; mt++)
            #pragma unroll
            for (int nt = 0; nt < 2; nt++)
                #pragma unroll
                for (int r = 0; r < 4; r++)
                    o[mt][nt][r] *= scale[mt][r >> 1];

        // O += P @ V  (B operand from V^T: row d, k-contig kv)
        #pragma unroll
        for (int kk = 0; kk < 4; kk++) {
            const int kb = kk * 8;
            uint32_t pa[2][4];
            #pragma unroll
            for (int mt = 0; mt < 2; mt++) {
                const uint32_t* p0 = Ps + (wrow + mt * 16 + g) * LDW + kb + t;
                const uint32_t* p1 = p0 + 8 * LDW;
                pa[mt][0] = p0[0]; pa[mt][1] = p1[0];
                pa[mt][2] = p0[4]; pa[mt][3] = p1[4];
            }
            uint32_t vb[2][2];
            #pragma unroll
            for (int nt = 0; nt < 2; nt++) {
                const uint32_t* p = Vt + (wcol + nt * 8 + g) * LDW + kb + t;
                vb[nt][0] = p[0]; vb[nt][1] = p[4];
            }
            #pragma unroll
            for (int mt = 0; mt < 2; mt++)
                #pragma unroll
                for (int nt = 0; nt < 2; nt++)
                    mma_f16(o[mt][nt][0], o[mt][nt][1], o[mt][nt][2], o[mt][nt][3],
                            pa[mt][0], pa[mt][1], pa[mt][2], pa[mt][3],
                            vb[nt][0], vb[nt][1]);
        }
        __syncthreads();
    }

    // epilogue: leaky_relu(O/l) -> fp16 attn [B,N,H*DH]
    #pragma unroll
    for (int mt = 0; mt < 2; mt++)
        #pragma unroll
        for (int hf = 0; hf < 2; hf++) {
            const float inv = 1.0f / l_run[mt][hf];
            const int row = q0 + wrow + mt * 16 + hf * 8 + g;
            __half* dst = attn + ((size_t)b * N_ + row) * DM + h * DH_;
            #pragma unroll
            for (int nt = 0; nt < 2; nt++) {
                const int d = wcol + nt * 8 + 2 * t;
                float v0 = o[mt][nt][hf * 2 + 0] * inv;
                float v1 = o[mt][nt][hf * 2 + 1] * inv;
                v0 = v0 > 0.f ? v0 : 0.01f * v0;
                v1 = v1 > 0.f ? v1 : 0.01f * v1;
                __half2 hv = __floats2half2_rn(v0, v1);
                *reinterpret_cast<__half2*>(dst + d) = hv;
            }
        }
}

// ---------------------------------------------------------------------------
// fp16 mma GEMM: C = A(MxK) * B(NxK)^T. BM=128, BN=64, BK=32, 128 thr, 4 warps
// (warp tile 64x32), 2-stage cp.async. Rows padded to 20 b32 words.
//   EPI 1: QKV scatter (+bias) -> fp16 q/k/vT
//   EPI 4: +bias? +residual(e1) -> fp32 C
//   EPI 5: +bias, relu -> fp16 C
// ---------------------------------------------------------------------------
#define LDG_ 20
template<int EPI>
__global__ void __launch_bounds__(128, 4)
tc_gemm(const __half* __restrict__ A, const __half* __restrict__ Bw,
        const float* __restrict__ bias, void* __restrict__ Cv,
        int M, int N, int K,
        const float* __restrict__ e1)
{
    constexpr int THREADS = 128;
    constexpr int STG = (128 + 64) * LDG_;    // words per stage

    extern __shared__ uint32_t sw[];

    const int tid  = threadIdx.x;
    const int wid  = tid >> 5;
    const int lane = tid & 31;
    const int g    = lane >> 2;
    const int t    = lane & 3;
    const int wr   = (wid >> 1) * 64;
    const int wc   = (wid & 1) * 32;

    const int brow = blockIdx.y * 128;
    const int bcol = blockIdx.x * 64;
    const __half* Ab = A  + (size_t)brow * K;
    const __half* Bb = Bw + (size_t)bcol * K;

    float c[4][4][4];
    #pragma unroll
    for (int i = 0; i < 4; i++)
        #pragma unroll
        for (int j = 0; j < 4; j++)
            #pragma unroll
            for (int r = 0; r < 4; r++) c[i][j][r] = 0.0f;

    const uint32_t smb = smem_u32(sw);

    auto load_stage = [&](int s) {
        const int buf = s & 1;
        const uint32_t as = smb + (uint32_t)(buf * STG) * 4u;
        const uint32_t bs = as + 128u * LDG_ * 4u;
        const __half* ag = Ab + s * 32;
        #pragma unroll
        for (int i = tid; i < 128 * 4; i += THREADS) {
            const int r = i >> 2, q = i & 3;
            CP_ASYNC16(as + (uint32_t)(r * LDG_ + q * 4) * 4u,
                       ag + (size_t)r * K + q * 8);
        }
        const __half* bg = Bb + s * 32;
        #pragma unroll
        for (int i = tid; i < 64 * 4; i += THREADS) {
            const int r = i >> 2, q = i & 3;
            CP_ASYNC16(bs + (uint32_t)(r * LDG_ + q * 4) * 4u,
                       bg + (size_t)r * K + q * 8);
        }
        CP_COMMIT();
    };

    const int S = K / 32;
    load_stage(0);

    for (int s = 0; s < S; s++) {
        if (s + 1 < S) { load_stage(s + 1); cp_wait<1>(); }
        else           { cp_wait<0>(); }
        __syncthreads();

        const int buf = s & 1;
        const uint32_t* As32 = sw + buf * STG;
        const uint32_t* Bs32 = As32 + 128 * LDG_;

        #pragma unroll
        for (int ks = 0; ks < 2; ks++) {
            const int kb = ks * 8;
            uint32_t af[4][4];
            #pragma unroll
            for (int mt = 0; mt < 4; mt++) {
                const uint32_t* p0 = As32 + (wr + mt * 16 + g) * LDG_ + kb + t;
                const uint32_t* p1 = p0 + 8 * LDG_;
                af[mt][0] = p0[0]; af[mt][1] = p1[0];
                af[mt][2] = p0[4]; af[mt][3] = p1[4];
            }
            uint32_t bf[4][2];
            #pragma unroll
            for (int nt = 0; nt < 4; nt++) {
                const uint32_t* p = Bs32 + (wc + nt * 8 + g) * LDG_ + kb + t;
                bf[nt][0] = p[0]; bf[nt][1] = p[4];
            }
            #pragma unroll
            for (int mt = 0; mt < 4; mt++)
                #pragma unroll
                for (int nt = 0; nt < 4; nt++)
                    mma_f16(c[mt][nt][0], c[mt][nt][1], c[mt][nt][2], c[mt][nt][3],
                            af[mt][0], af[mt][1], af[mt][2], af[mt][3],
                            bf[nt][0], bf[nt][1]);
        }
        __syncthreads();
    }

    #pragma unroll
    for (int mt = 0; mt < 4; mt++) {
        #pragma unroll
        for (int half = 0; half < 2; half++) {
            const int row = brow + wr + mt * 16 + g + half * 8;
            #pragma unroll
            for (int nt = 0; nt < 4; nt++) {
                const int col = bcol + wc + nt * 8 + 2 * t;
                float v0 = c[mt][nt][half * 2 + 0];
                float v1 = c[mt][nt][half * 2 + 1];
                if constexpr (EPI == 1) {
                    v0 += bias[col]; v1 += bias[col + 1];
                    const int h  = col / (3 * DH_);
                    const int cc = col % (3 * DH_);
                    const int bb = row >> 10;
                    const int n  = row & (N_ - 1);
                    if (cc < DH_) {
                        __half* base = g_hvT + ((size_t)(bb * H_ + h) * DH_ + cc) * N_ + n;
                        base[0]  = __float2half(v0);
                        base[N_] = __float2half(v1);
                    } else if (cc < 2 * DH_) {
                        *reinterpret_cast<__half2*>(
                            g_hq + ((size_t)(bb * H_ + h) * N_ + n) * DH_ + (cc - DH_)) =
                            __floats2half2_rn(v0, v1);
                    } else {
                        *reinterpret_cast<__half2*>(
                            g_hk + ((size_t)(bb * H_ + h) * N_ + n) * DH_ + (cc - 2 * DH_)) =
                            __floats2half2_rn(v0, v1);
                    }
                } else if constexpr (EPI == 4) {
                    float* C = (float*)Cv;
                    if (bias) { v0 += bias[col]; v1 += bias[col + 1]; }
                    float2 r2 = *reinterpret_cast<const float2*>(e1 + (size_t)row * N + col);
                    *reinterpret_cast<float2*>(C + (size_t)row * N + col) =
                        make_float2(v0 + r2.x, v1 + r2.y);
                } else {  // EPI 5: relu -> fp16
                    __half* C = (__half*)Cv;
                    v0 += bias[col]; v1 += bias[col + 1];
                    *reinterpret_cast<__half2*>(C + (size_t)row * N + col) =
                        __floats2half2_rn(fmaxf(v0, 0.f), fmaxf(v1, 0.f));
                }
            }
        }
    }
}

// ---------------------------------------------------------------------------
// Launch
// ---------------------------------------------------------------------------
extern "C" void kernel_launch(void* const* d_in, const int* in_sizes, int n_in,
                              void* d_out, int out_size)
{
    const float* Z        = (const float*)d_in[0];
    const float* Dm       = (const float*)d_in[1];
    const float* new_mask = (const float*)d_in[2];
    const float* mask     = (const float*)d_in[3];
    const float* Wqkv     = (const float*)d_in[4];
    const float* bqkv     = (const float*)d_in[5];
    const float* Wo       = (const float*)d_in[6];
    const float* g1       = (const float*)d_in[7];
    const float* b1       = (const float*)d_in[8];
    const float* g2       = (const float*)d_in[9];
    const float* b2       = (const float*)d_in[10];
    const float* Wp1      = (const float*)d_in[11];
    const float* bp1      = (const float*)d_in[12];
    const float* Wp2      = (const float*)d_in[13];
    const float* bp2      = (const float*)d_in[14];
    const float* gamma    = (const float*)d_in[15];
    float* out = (float*)d_out;

    __half *pZnh, *pattnh, *pZn2h, *pHidh, *phWqkv, *phWo, *phWp1, *phWp2;
    float *pZ2;
    cudaGetSymbolAddress((void**)&pZnh,   g_Znh);
    cudaGetSymbolAddress((void**)&pattnh, g_attnh);
    cudaGetSymbolAddress((void**)&pZ2,    g_Z2);
    cudaGetSymbolAddress((void**)&pZn2h,  g_Zn2h);
    cudaGetSymbolAddress((void**)&pHidh,  g_Hidh);
    cudaGetSymbolAddress((void**)&phWqkv, g_hWqkv);
    cudaGetSymbolAddress((void**)&phWo,   g_hWo);
    cudaGetSymbolAddress((void**)&phWp1,  g_hWp1);
    cudaGetSymbolAddress((void**)&phWp2,  g_hWp2);

    const int SMG   = 2 * (128 + 64) * LDG_ * 4;            // 30720
    const int SMATT = (4 * 64 * LDW) * 4 + 512 * 4;         // 38912
    cudaFuncSetAttribute(tc_gemm<1>, cudaFuncAttributeMaxDynamicSharedMemorySize, SMG);
    cudaFuncSetAttribute(tc_gemm<4>, cudaFuncAttributeMaxDynamicSharedMemorySize, SMG);
    cudaFuncSetAttribute(tc_gemm<5>, cudaFuncAttributeMaxDynamicSharedMemorySize, SMG);
    cudaFuncSetAttribute(attn_kernel, cudaFuncAttributeMaxDynamicSharedMemorySize, SMATT);

    // 0) Convert weights to fp16
    f2h_kernel<<<(QKV3*DM/4 + 255)/256, 256>>>(Wqkv, phWqkv, QKV3*DM/4);
    f2h_kernel<<<(DM*DM/4   + 255)/256, 256>>>(Wo,   phWo,   DM*DM/4);
    f2h_kernel<<<(DI*DM/4   + 255)/256, 256>>>(Wp1,  phWp1,  DI*DM/4);
    f2h_kernel<<<(DM*DI/4   + 255)/256, 256>>>(Wp2,  phWp2,  DM*DI/4);

    // 1) LN1 -> fp16
    ln_kernel<<<MROWS, 128>>>(Z, g1, b1, pZnh);

    // 2) QKV -> fp16 q/k/vT
    tc_gemm<1><<<dim3(QKV3/64, MROWS/128), 128, SMG>>>(
        pZnh, phWqkv, bqkv, nullptr, MROWS, QKV3, DM, nullptr);

    // 3) Flash attention -> fp16 attn
    attn_kernel<<<dim3(N_/64, B_*H_), 256, SMATT>>>(
        new_mask, Dm, mask, gamma, pattnh);

    // 4) Wo + residual -> fp32 Z2
    tc_gemm<4><<<dim3(DM/64, MROWS/128), 128, SMG>>>(
        pattnh, phWo, nullptr, pZ2, MROWS, DM, DM, Z);

    // 5) LN2 -> fp16
    ln_kernel<<<MROWS, 128>>>(pZ2, g2, b2, pZn2h);

    // 6) MLP1 + relu -> fp16 Hid
    tc_gemm<5><<<dim3(DI/64, MROWS/128), 128, SMG>>>(
        pZn2h, phWp1, bp1, pHidh, MROWS, DI, DM, nullptr);

    // 7) MLP2 + bias + residual -> fp32 out
    tc_gemm<4><<<dim3(DM/64, MROWS/128), 128, SMG>>>(
        pHidh, phWp2, bp2, out, MROWS, DM, DI, pZ2);
}